// round 12
// baseline (speedup 1.0000x reference)
#include <cuda_runtime.h>
#include <cuda_bf16.h>
#include <cstdint>

// QuantumFeatureMap closed form: t_q = cos(1.57*x_q), row outputs:
//   [t1t2t3, t0t1, t0t1t2, t0t1t2t3, t0t2t3, t0t3, t0, t2, t2t3, t3]
//
// R9 -> R10: R7 skeleton (best: 1024 CTAs x 4 tiles, front-batched cp.async
// input ring, warp-local smem staging, coalesced STG.128) + L2::evict_last
// cache-hint on the input cp.async loads. The 56MB working set (16MB in +
// 40MB out) fits in the 126MB L2; pinning the input evict-last should make
// steady-state graph replays run L2-resident with ~zero DRAM read traffic.

#define QFM_ALPHA 1.57f
#define QFM_BLOCK 256
#define QFM_ITERS 4

template <int N>
__device__ __forceinline__ void cp_wait_group() {
    asm volatile("cp.async.wait_group %0;\n" :: "n"(N) : "memory");
}

__global__ void __launch_bounds__(QFM_BLOCK)
qfm_kernel(const float4* __restrict__ x, float4* __restrict__ out)
{
    __shared__ __align__(16) float4 ins[QFM_ITERS][QFM_BLOCK];  // 16 KB input ring
    __shared__ __align__(16) float  st[QFM_BLOCK * 10];         // 10 KB store staging

    const int tid  = threadIdx.x;
    const int warp = tid >> 5;
    const int lane = tid & 31;
    const int tile0 = blockIdx.x * QFM_ITERS;

    // L2 evict-last policy for the input stream (keep resident across replays).
    uint64_t policy;
    asm volatile("createpolicy.fractional.L2::evict_last.b64 %0, 1.0;\n"
                 : "=l"(policy));

    // Front-batch all tile loads: 4 x 16B cp.async per thread, one group each.
    #pragma unroll
    for (int it = 0; it < QFM_ITERS; ++it) {
        uint32_t dst = (uint32_t)__cvta_generic_to_shared(&ins[it][tid]);
        const float4* src = x + (size_t)(tile0 + it) * QFM_BLOCK + tid;
        asm volatile("cp.async.cg.shared.global.L2::cache_hint [%0], [%1], 16, %2;\n"
                     :: "r"(dst), "l"(src), "l"(policy) : "memory");
        asm volatile("cp.async.commit_group;\n" ::: "memory");
    }

    float*  ws  = st + warp * 320;            // warp's 32 rows * 10 floats
    float4* wsv = (float4*)ws;                // 80 float4
    float2* wsp = (float2*)(ws + lane * 10);  // this lane's row (40B)

    #pragma unroll
    for (int it = 0; it < QFM_ITERS; ++it) {
        // Wait until this tile's group has landed (later groups stay in flight).
        if      (it == 0) cp_wait_group<QFM_ITERS - 1>();
        else if (it == 1) cp_wait_group<QFM_ITERS - 2>();
        else if (it == 2) cp_wait_group<QFM_ITERS - 3>();
        else              cp_wait_group<0>();

        float4 v = ins[it][tid];              // own bytes -> no barrier needed

        float t0 = __cosf(QFM_ALPHA * v.x);
        float t1 = __cosf(QFM_ALPHA * v.y);
        float t2 = __cosf(QFM_ALPHA * v.z);
        float t3 = __cosf(QFM_ALPHA * v.w);

        float t01 = t0 * t1;
        float t23 = t2 * t3;

        wsp[0] = make_float2(t1 * t23, t01);        // out0, out1
        wsp[1] = make_float2(t01 * t2, t01 * t23);  // out2, out3
        wsp[2] = make_float2(t0 * t23, t0 * t3);    // out4, out5
        wsp[3] = make_float2(t0, t2);               // out6, out7
        wsp[4] = make_float2(t23, t3);              // out8, out9

        __syncwarp();

        // Warp's output span: 32 rows * 40B = 1280B contiguous = 80 float4.
        // Fully coalesced STG.128.
        float4* o = out + (size_t)(tile0 + it) * 640 + warp * 80;
        o[lane]      = wsv[lane];
        o[lane + 32] = wsv[lane + 32];
        if (lane < 16)
            o[lane + 64] = wsv[lane + 64];

        __syncwarp();   // protect staging reuse next iteration
    }
}

extern "C" void kernel_launch(void* const* d_in, const int* in_sizes, int n_in,
                              void* d_out, int out_size)
{
    const float4* x = (const float4*)d_in[0];
    float4* out = (float4*)d_out;

    const int n_rows = in_sizes[0] / 4;                   // 1048576
    const int grid = n_rows / (QFM_BLOCK * QFM_ITERS);    // 1024 CTAs

    qfm_kernel<<<grid, QFM_BLOCK>>>(x, out);
}

// round 15
// speedup vs baseline: 1.3874x; 1.3874x over previous
#include <cuda_runtime.h>
#include <cuda_bf16.h>
#include <cstdint>

// QuantumFeatureMap closed form: t_q = cos(1.57*x_q), row outputs:
//   [t1t2t3, t0t1, t0t1t2, t0t1t2t3, t0t2t3, t0t3, t0, t2, t2t3, t3]
//
// R12 -> R13: revert evict_last (hurt steady-state replays). R7 structure with
// ITERS=2 / grid=2048: smem 18KB -> 8 CTAs/SM (2048 thr = 100% theoretical
// occupancy), ~2 waves so CTA finish-skew overlaps. Default cache policy.

#define QFM_ALPHA 1.57f
#define QFM_BLOCK 256
#define QFM_ITERS 2

template <int N>
__device__ __forceinline__ void cp_wait_group() {
    asm volatile("cp.async.wait_group %0;\n" :: "n"(N) : "memory");
}

__global__ void __launch_bounds__(QFM_BLOCK)
qfm_kernel(const float4* __restrict__ x, float4* __restrict__ out)
{
    __shared__ __align__(16) float4 ins[QFM_ITERS][QFM_BLOCK];  // 8 KB input ring
    __shared__ __align__(16) float  st[QFM_BLOCK * 10];         // 10 KB store staging

    const int tid  = threadIdx.x;
    const int warp = tid >> 5;
    const int lane = tid & 31;
    const int tile0 = blockIdx.x * QFM_ITERS;

    // Front-batch both tile loads: 2 x 16B cp.async per thread, one group each.
    #pragma unroll
    for (int it = 0; it < QFM_ITERS; ++it) {
        uint32_t dst = (uint32_t)__cvta_generic_to_shared(&ins[it][tid]);
        const float4* src = x + (size_t)(tile0 + it) * QFM_BLOCK + tid;
        asm volatile("cp.async.cg.shared.global [%0], [%1], 16;\n"
                     :: "r"(dst), "l"(src) : "memory");
        asm volatile("cp.async.commit_group;\n" ::: "memory");
    }

    float*  ws  = st + warp * 320;            // warp's 32 rows * 10 floats
    float4* wsv = (float4*)ws;                // 80 float4
    float2* wsp = (float2*)(ws + lane * 10);  // this lane's row (40B)

    #pragma unroll
    for (int it = 0; it < QFM_ITERS; ++it) {
        // Wait until this tile's group has landed (later group stays in flight).
        if (it == 0) cp_wait_group<QFM_ITERS - 1>();
        else         cp_wait_group<0>();

        float4 v = ins[it][tid];              // own bytes -> no barrier needed

        float t0 = __cosf(QFM_ALPHA * v.x);
        float t1 = __cosf(QFM_ALPHA * v.y);
        float t2 = __cosf(QFM_ALPHA * v.z);
        float t3 = __cosf(QFM_ALPHA * v.w);

        float t01 = t0 * t1;
        float t23 = t2 * t3;

        wsp[0] = make_float2(t1 * t23, t01);        // out0, out1
        wsp[1] = make_float2(t01 * t2, t01 * t23);  // out2, out3
        wsp[2] = make_float2(t0 * t23, t0 * t3);    // out4, out5
        wsp[3] = make_float2(t0, t2);               // out6, out7
        wsp[4] = make_float2(t23, t3);              // out8, out9

        __syncwarp();

        // Warp's output span: 32 rows * 40B = 1280B contiguous = 80 float4.
        // Fully coalesced STG.128.
        float4* o = out + (size_t)(tile0 + it) * 640 + warp * 80;
        o[lane]      = wsv[lane];
        o[lane + 32] = wsv[lane + 32];
        if (lane < 16)
            o[lane + 64] = wsv[lane + 64];

        __syncwarp();   // protect staging reuse next iteration
    }
}

extern "C" void kernel_launch(void* const* d_in, const int* in_sizes, int n_in,
                              void* d_out, int out_size)
{
    const float4* x = (const float4*)d_in[0];
    float4* out = (float4*)d_out;

    const int n_rows = in_sizes[0] / 4;                   // 1048576
    const int grid = n_rows / (QFM_BLOCK * QFM_ITERS);    // 2048 CTAs

    qfm_kernel<<<grid, QFM_BLOCK>>>(x, out);
}